// round 6
// baseline (speedup 1.0000x reference)
#include <cuda_runtime.h>
#include <cuda_fp16.h>
#include <mma.h>
#include <math.h>
#include <stdint.h>

using namespace nvcuda;

#define NB    4096
#define NFG_  1024
#define NFP_  256
#define NFR_  256
#define NG_   4
#define FPPD  1280
#define THR2  302.76f                      // (0.2*87)^2
#define SIMSCALE 0.044194173824159216f     // 1/sqrt(512)

// ---------------- device scratch (static, allocation-free) ----------------
__device__ float  g_foot[NB * 2];
__device__ __half g_fpp_h [(size_t)NB * FPPD];
__device__ __half g_thW_h [(size_t)NG_ * FPPD * NFR_];
__device__ __half g_phW_h [(size_t)NG_ * FPPD * NFR_];
__device__ __half g_gwW_h [(size_t)NG_ * NFG_ * NFG_];
__device__ __half g_ft_h  [(size_t)NB * NFG_];
__device__ __half g_theta_h[(size_t)NG_ * NB * NFR_];
__device__ __half g_phi_h  [(size_t)NG_ * NB * NFR_];
__device__ __half g_A_h  [(size_t)NG_ * NB * NB];        // sim fp16 -> A in place
__device__ __half g_agg_h[(size_t)NG_ * NB * NFG_];
__device__ float  g_outp [(size_t)NG_ * NB * NFG_];

// ---------------- cp.async helpers ----------------
__device__ __forceinline__ void cp_async16(void* smem_dst, const void* gmem_src) {
    unsigned s = (unsigned)__cvta_generic_to_shared(smem_dst);
    asm volatile("cp.async.cg.shared.global [%0], [%1], 16;\n" :: "r"(s), "l"(gmem_src));
}
#define CP_COMMIT() asm volatile("cp.async.commit_group;\n" ::: "memory")

// ---------------- foot points ----------------
__global__ void foot_kernel(const float* __restrict__ boxes, float* __restrict__ foot) {
    int n = blockIdx.x * 256 + threadIdx.x;
    if (n < NB) {
        foot[2 * n]     = (boxes[4 * n + 0] + boxes[4 * n + 2]) * 0.5f;
        foot[2 * n + 1] = boxes[4 * n + 3];
    }
}

// ---------------- fpp (fp16) = [sincos_emb(foot,256) | feats] ----------------
__global__ void fpp_kernel(const float* __restrict__ feats,
                           const float* __restrict__ foot,
                           __half* __restrict__ fpp) {
    long long idx = (long long)blockIdx.x * 256 + threadIdx.x;
    if (idx >= (long long)NB * FPPD) return;
    int n = (int)(idx / FPPD);
    int j = (int)(idx % FPPD);
    float v;
    if (j < NFP_) {
        int coord = j / 128;
        int jj = j % 128;
        int i = jj & 63;
        bool is_cos = jj >= 64;
        float freq = expf(-(float)i * 0.14391157750382243f);  // 10000^(-i/64)
        float ang = foot[2 * n + coord] * freq;
        v = is_cos ? cosf(ang) : sinf(ang);
    } else {
        v = feats[(long long)n * NFG_ + (j - NFP_)];
    }
    fpp[idx] = __float2half(v);
}

// ---------------- elementwise fp32 -> fp16 ----------------
__global__ void conv_kernel(const float* __restrict__ in, __half* __restrict__ out, long long n) {
    long long i = ((long long)blockIdx.x * 256 + threadIdx.x) * 4;
    if (i >= n) return;
    float4 v = *(const float4*)(in + i);
    __half2 h0 = __floats2half2_rn(v.x, v.y);
    __half2 h1 = __floats2half2_rn(v.z, v.w);
    *(uint2*)(out + i) = make_uint2(*(uint32_t*)&h0, *(uint32_t*)&h1);
}

// ======================= fp16 wmma GEMM v2 =======================
// 128x256 block tile, 8 warps (2x4) of 64x64, BK=32, double-buffered cp.async.
// TRANSB=0: B is [K,N] row-major; TRANSB=1: B is [N,K] row-major (A @ B^T).
// OUTH=1: fp16 output via smem staging (+optional per-column BIAS); OUTH=0: fp32.
#define GBM 128
#define GBN 256
#define GBK 32
#define APITCH 40      // halves per A-tile row (32+8)
#define BPITCH_NT 264  // halves per B-tile row, non-trans (256+8)
#define A_HALVES (GBM * APITCH)                    // 5120
#define BT_HALVES (GBN * APITCH)                   // trans: 256 x 40 = 10240
#define BNT_HALVES (GBK * BPITCH_NT)               // 32 x 264 = 8448
#define SMEM_NT ((A_HALVES + BNT_HALVES) * 2 * 2)  // 54272 B
#define SMEM_T  ((A_HALVES + BT_HALVES) * 2 * 2)   // 61440 B

template<int TRANSB, int OUTH, int BIAS>
__global__ __launch_bounds__(256)
void hgemm_kernel(const __half* __restrict__ Aall, const __half* __restrict__ Ball,
                  float* __restrict__ Cfall, __half* __restrict__ Chall,
                  const float* __restrict__ bias,
                  int M, int N, int K,
                  long long sA, long long sB, long long sC)
{
    extern __shared__ char dsm[];
    __half* As = (__half*)dsm;                              // 2 x A_HALVES
    __half* Bs = (__half*)dsm + 2 * A_HALVES;
    const int BTILE = TRANSB ? BT_HALVES : BNT_HALVES;

    int g = blockIdx.z;
    const __half* A = Aall + (long long)g * sA;
    const __half* B = Ball + (long long)g * sB;

    int tid = threadIdx.x;
    int wid = tid >> 5, lane = tid & 31;
    int wr = wid >> 2;      // 0..1 -> 64-row group
    int wc = wid & 3;       // 0..3 -> 64-col group
    int rowBase = blockIdx.y * GBM;
    int colBase = blockIdx.x * GBN;

    using FragA  = wmma::fragment<wmma::matrix_a, 16, 16, 16, __half, wmma::row_major>;
    using FragBr = wmma::fragment<wmma::matrix_b, 16, 16, 16, __half, wmma::row_major>;
    using FragBc = wmma::fragment<wmma::matrix_b, 16, 16, 16, __half, wmma::col_major>;
    using FragC  = wmma::fragment<wmma::accumulator, 16, 16, 16, float>;

    FragC acc[4][4];
    #pragma unroll
    for (int i = 0; i < 4; i++)
        #pragma unroll
        for (int j = 0; j < 4; j++)
            wmma::fill_fragment(acc[i][j], 0.0f);

    int KT = K / GBK;

    // A tile: 512 x 16B units (2/thread). B tile: 1024 units (4/thread).
    #define ISSUE(kt, buf) {                                                             \
        int k0 = (kt) * GBK;                                                             \
        _Pragma("unroll")                                                                \
        for (int q = 0; q < 2; q++) {                                                    \
            int u = tid * 2 + q;                                                         \
            int ar = u >> 2, ac = (u & 3) * 8;                                           \
            cp_async16(As + (buf) * A_HALVES + ar * APITCH + ac,                         \
                       A + (long long)(rowBase + ar) * K + k0 + ac);                     \
        }                                                                                \
        _Pragma("unroll")                                                                \
        for (int q = 0; q < 4; q++) {                                                    \
            int u = tid * 4 + q;                                                         \
            if (TRANSB) {                                                                \
                int br = u >> 2, bc = (u & 3) * 8;                                       \
                cp_async16(Bs + (buf) * BTILE + br * APITCH + bc,                        \
                           B + (long long)(colBase + br) * K + k0 + bc);                 \
            } else {                                                                     \
                int br = u >> 5, bc = (u & 31) * 8;                                      \
                cp_async16(Bs + (buf) * BTILE + br * BPITCH_NT + bc,                     \
                           B + (long long)(k0 + br) * N + colBase + bc);                 \
            }                                                                            \
        }                                                                                \
    }

    ISSUE(0, 0); CP_COMMIT();

    for (int kt = 0; kt < KT; kt++) {
        int buf = kt & 1;
        if (kt + 1 < KT) {
            ISSUE(kt + 1, buf ^ 1); CP_COMMIT();
            asm volatile("cp.async.wait_group 1;\n" ::: "memory");
        } else {
            asm volatile("cp.async.wait_group 0;\n" ::: "memory");
        }
        __syncthreads();

        #pragma unroll
        for (int ks = 0; ks < 2; ks++) {
            FragA af[4];
            #pragma unroll
            for (int i = 0; i < 4; i++)
                wmma::load_matrix_sync(af[i],
                    As + buf * A_HALVES + (wr * 64 + i * 16) * APITCH + ks * 16, APITCH);
            #pragma unroll
            for (int j = 0; j < 4; j++) {
                if (TRANSB) {
                    FragBc bf;
                    wmma::load_matrix_sync(bf,
                        Bs + buf * BTILE + (wc * 64 + j * 16) * APITCH + ks * 16, APITCH);
                    #pragma unroll
                    for (int i = 0; i < 4; i++)
                        wmma::mma_sync(acc[i][j], af[i], bf, acc[i][j]);
                } else {
                    FragBr bf;
                    wmma::load_matrix_sync(bf,
                        Bs + buf * BTILE + (ks * 16) * BPITCH_NT + wc * 64 + j * 16, BPITCH_NT);
                    #pragma unroll
                    for (int i = 0; i < 4; i++)
                        wmma::mma_sync(acc[i][j], af[i], bf, acc[i][j]);
                }
            }
        }
        __syncthreads();
    }

    if (OUTH) {
        // stage 16x64 f32 per warp in smem, convert (+bias) -> fp16, vector store
        __half* Ch = Chall + (long long)g * sC;
        float* stage = (float*)dsm + wid * (16 * 72);
        const float* bi = BIAS ? (bias + (long long)g * N) : nullptr;
        int r = lane >> 1, c0 = (lane & 1) * 32;
        int gcolW = colBase + wc * 64;
        #pragma unroll 1
        for (int i = 0; i < 4; i++) {
            #pragma unroll
            for (int j = 0; j < 4; j++)
                wmma::store_matrix_sync(stage + j * 16, acc[i][j], 72, wmma::mem_row_major);
            __syncwarp();
            int grow = rowBase + wr * 64 + i * 16 + r;
            __align__(16) __half2 hbuf[16];
            #pragma unroll
            for (int k = 0; k < 16; k++) {
                float v0 = stage[r * 72 + c0 + 2 * k];
                float v1 = stage[r * 72 + c0 + 2 * k + 1];
                if (BIAS) {
                    v0 += bi[gcolW + c0 + 2 * k];
                    v1 += bi[gcolW + c0 + 2 * k + 1];
                }
                hbuf[k] = __floats2half2_rn(v0, v1);
            }
            uint4* dst = (uint4*)(Ch + (long long)grow * N + gcolW + c0);
            #pragma unroll
            for (int q = 0; q < 4; q++) dst[q] = ((const uint4*)hbuf)[q];
            __syncwarp();
        }
    } else {
        float* C = Cfall + (long long)g * sC;
        #pragma unroll
        for (int i = 0; i < 4; i++)
            #pragma unroll
            for (int j = 0; j < 4; j++)
                wmma::store_matrix_sync(
                    C + (long long)(rowBase + wr * 64 + i * 16) * N + colBase + wc * 64 + j * 16,
                    acc[i][j], N, wmma::mem_row_major);
    }
    #undef ISSUE
}

// ---------------- fused scale + mask + row softmax, fp16 in-place ----------------
__global__ void softmax_kernel(__half* __restrict__ Ah, const float* __restrict__ foot) {
    int n = blockIdx.x;
    long long base = ((long long)blockIdx.y * NB + n) * NB;
    __half2* row2 = (__half2*)(Ah + base);
    __shared__ float red[256];
    int tid = threadIdx.x;
    float frx = foot[2 * n], fry = foot[2 * n + 1];

    float v0[8], v1[8];
    float m = -INFINITY;
    #pragma unroll
    for (int i = 0; i < 8; i++) {
        int p = tid + i * 256;                  // half2 index, column pair (2p, 2p+1)
        float2 s = __half22float2(row2[p]);
        int c = 2 * p;
        float dx0 = frx - foot[2 * c],     dy0 = fry - foot[2 * c + 1];
        float dx1 = frx - foot[2 * c + 2], dy1 = fry - foot[2 * c + 3];
        v0[i] = (dx0 * dx0 + dy0 * dy0 > THR2) ? -INFINITY : s.x * SIMSCALE;
        v1[i] = (dx1 * dx1 + dy1 * dy1 > THR2) ? -INFINITY : s.y * SIMSCALE;
        m = fmaxf(m, fmaxf(v0[i], v1[i]));
    }
    red[tid] = m; __syncthreads();
    for (int s = 128; s > 0; s >>= 1) { if (tid < s) red[tid] = fmaxf(red[tid], red[tid + s]); __syncthreads(); }
    m = red[0]; __syncthreads();
    float sum = 0.0f;
    #pragma unroll
    for (int i = 0; i < 8; i++) {
        v0[i] = __expf(v0[i] - m); v1[i] = __expf(v1[i] - m);
        sum += v0[i] + v1[i];
    }
    red[tid] = sum; __syncthreads();
    for (int s = 128; s > 0; s >>= 1) { if (tid < s) red[tid] += red[tid + s]; __syncthreads(); }
    float inv = 1.0f / red[0];
    #pragma unroll
    for (int i = 0; i < 8; i++)
        row2[tid + i * 256] = __floats2half2_rn(v0[i] * inv, v1[i] * inv);
}

// ---------------- final_graph = min(1, mean_g A) ----------------
__global__ void fg_kernel(const __half* __restrict__ Ah, float* __restrict__ fg) {
    long long p = (long long)blockIdx.x * 256 + threadIdx.x;   // half2 index
    const long long PER_G2 = (long long)NB * NB / 2;
    const __half2* a2 = (const __half2*)Ah;
    float2 s0 = __half22float2(a2[p]);
    float2 s1 = __half22float2(a2[p + PER_G2]);
    float2 s2 = __half22float2(a2[p + 2 * PER_G2]);
    float2 s3 = __half22float2(a2[p + 3 * PER_G2]);
    float2 r;
    r.x = fminf(0.25f * (s0.x + s1.x + s2.x + s3.x), 1.0f);
    r.y = fminf(0.25f * (s0.y + s1.y + s2.y + s3.y), 1.0f);
    *(float2*)(fg + 2 * p) = r;
}

// ---------------- LayerNorm + ReLU + sum over g ----------------
__global__ void ln_kernel(const float* __restrict__ outp,
                          const float* __restrict__ gamma,
                          const float* __restrict__ beta,
                          float* __restrict__ out) {
    int n = blockIdx.x;
    int tid = threadIdx.x;  // 256
    __shared__ float red[256];
    float accum[4] = {0.f, 0.f, 0.f, 0.f};
    for (int g = 0; g < NG_; g++) {
        const float* row = outp + ((long long)g * NB + n) * NFG_;
        float v[4];
        float s = 0.0f;
        #pragma unroll
        for (int i = 0; i < 4; i++) { v[i] = row[tid + i * 256]; s += v[i]; }
        red[tid] = s; __syncthreads();
        for (int st = 128; st > 0; st >>= 1) { if (tid < st) red[tid] += red[tid + st]; __syncthreads(); }
        float mean = red[0] * (1.0f / NFG_); __syncthreads();
        float s2 = 0.0f;
        #pragma unroll
        for (int i = 0; i < 4; i++) { float d = v[i] - mean; s2 += d * d; }
        red[tid] = s2; __syncthreads();
        for (int st = 128; st > 0; st >>= 1) { if (tid < st) red[tid] += red[tid + st]; __syncthreads(); }
        float inv = rsqrtf(red[0] * (1.0f / NFG_) + 1e-5f);
        __syncthreads();
        #pragma unroll
        for (int i = 0; i < 4; i++) {
            int c = tid + i * 256;
            float y = (v[i] - mean) * inv * gamma[g * NFG_ + c] + beta[g * NFG_ + c];
            accum[i] += fmaxf(y, 0.0f);
        }
    }
    #pragma unroll
    for (int i = 0; i < 4; i++)
        out[(long long)n * NFG_ + tid + i * 256] = accum[i];
}

// ======================= launch =======================
extern "C" void kernel_launch(void* const* d_in, const int* in_sizes, int n_in,
                              void* d_out, int out_size) {
    const float* feats   = (const float*)d_in[0];
    const float* boxes   = (const float*)d_in[1];
    const float* theta_w = (const float*)d_in[2];
    const float* theta_b = (const float*)d_in[3];
    const float* phi_w   = (const float*)d_in[4];
    const float* phi_b   = (const float*)d_in[5];
    const float* gcn_w   = (const float*)d_in[6];
    const float* ln_g    = (const float*)d_in[7];
    const float* ln_b    = (const float*)d_in[8];
    float* out = (float*)d_out;   // [4096*1024] out ++ [4096*4096] final_graph

    float *p_foot, *p_outp;
    __half *p_fpp, *p_thW, *p_phW, *p_gwW, *p_ft, *p_theta, *p_phi, *p_Ah, *p_agg;
    cudaGetSymbolAddress((void**)&p_foot, g_foot);
    cudaGetSymbolAddress((void**)&p_fpp,  g_fpp_h);
    cudaGetSymbolAddress((void**)&p_thW,  g_thW_h);
    cudaGetSymbolAddress((void**)&p_phW,  g_phW_h);
    cudaGetSymbolAddress((void**)&p_gwW,  g_gwW_h);
    cudaGetSymbolAddress((void**)&p_ft,   g_ft_h);
    cudaGetSymbolAddress((void**)&p_theta, g_theta_h);
    cudaGetSymbolAddress((void**)&p_phi,  g_phi_h);
    cudaGetSymbolAddress((void**)&p_Ah,   g_A_h);
    cudaGetSymbolAddress((void**)&p_agg,  g_agg_h);
    cudaGetSymbolAddress((void**)&p_outp, g_outp);

    cudaFuncSetAttribute(hgemm_kernel<0,1,1>, cudaFuncAttributeMaxDynamicSharedMemorySize, SMEM_NT);
    cudaFuncSetAttribute(hgemm_kernel<1,1,0>, cudaFuncAttributeMaxDynamicSharedMemorySize, SMEM_T);
    cudaFuncSetAttribute(hgemm_kernel<0,1,0>, cudaFuncAttributeMaxDynamicSharedMemorySize, SMEM_NT);
    cudaFuncSetAttribute(hgemm_kernel<0,0,0>, cudaFuncAttributeMaxDynamicSharedMemorySize, SMEM_NT);

    // 1) foot + fpp(fp16)
    foot_kernel<<<(NB + 255) / 256, 256>>>(boxes, p_foot);
    long long fppN = (long long)NB * FPPD;
    fpp_kernel<<<(unsigned)((fppN + 255) / 256), 256>>>(feats, p_foot, p_fpp);

    // 2) fp16 operand conversions
    {
        long long nw = (long long)NG_ * FPPD * NFR_;
        conv_kernel<<<(unsigned)(nw / 4 / 256), 256>>>(theta_w, p_thW, nw);
        conv_kernel<<<(unsigned)(nw / 4 / 256), 256>>>(phi_w, p_phW, nw);
        long long ng = (long long)NG_ * NFG_ * NFG_;
        conv_kernel<<<(unsigned)(ng / 4 / 256), 256>>>(gcn_w, p_gwW, ng);
        long long nf = (long long)NB * NFG_;
        conv_kernel<<<(unsigned)(nf / 4 / 256), 256>>>(feats, p_ft, nf);
    }

    // 3) theta/phi: [4096,1280] @ [1280,256] + bias -> fp16 (fused epilogue)
    {
        dim3 grid(NFR_ / GBN, NB / GBM, NG_);   // (1, 32, 4)
        hgemm_kernel<0,1,1><<<grid, 256, SMEM_NT>>>(p_fpp, p_thW, nullptr, p_theta, theta_b,
                                                    NB, NFR_, FPPD,
                                                    0, (long long)FPPD * NFR_, (long long)NB * NFR_);
        hgemm_kernel<0,1,1><<<grid, 256, SMEM_NT>>>(p_fpp, p_phW, nullptr, p_phi, phi_b,
                                                    NB, NFR_, FPPD,
                                                    0, (long long)FPPD * NFR_, (long long)NB * NFR_);
    }

    // 4) sim = theta @ phi^T -> fp16 (in A buffer)
    {
        dim3 grid(NB / GBN, NB / GBM, NG_);     // (16, 32, 4)
        hgemm_kernel<1,1,0><<<grid, 256, SMEM_T>>>(p_theta, p_phi, nullptr, p_Ah, nullptr,
                                                   NB, NB, NFR_,
                                                   (long long)NB * NFR_, (long long)NB * NFR_,
                                                   (long long)NB * NB);
    }

    // 5) softmax (scale + mask fused), fp16 in-place
    softmax_kernel<<<dim3(NB, NG_), 256>>>(p_Ah, p_foot);

    // 6) final_graph
    fg_kernel<<<(NB * NB / 2) / 256, 256>>>(p_Ah, out + (long long)NB * NFG_);

    // 7) agg = A @ feats -> fp16 (fused epilogue)
    {
        dim3 grid(NFG_ / GBN, NB / GBM, NG_);   // (4, 32, 4)
        hgemm_kernel<0,1,0><<<grid, 256, SMEM_NT>>>(p_Ah, p_ft, nullptr, p_agg, nullptr,
                                                    NB, NFG_, NB,
                                                    (long long)NB * NB, 0, (long long)NB * NFG_);
    }

    // 8) outp = agg @ gcn_w -> fp32
    {
        dim3 grid(NFG_ / GBN, NB / GBM, NG_);   // (4, 32, 4)
        hgemm_kernel<0,0,0><<<grid, 256, SMEM_NT>>>(p_agg, p_gwW, p_outp, nullptr, nullptr,
                                                    NB, NFG_, NFG_,
                                                    (long long)NB * NFG_, (long long)NFG_ * NFG_,
                                                    (long long)NB * NFG_);
    }

    // 9) LN + ReLU + sum over g
    ln_kernel<<<NB, 256>>>(p_outp, ln_g, ln_b, out);
}

// round 7
// speedup vs baseline: 3.6110x; 3.6110x over previous
#include <cuda_runtime.h>
#include <cuda_fp16.h>
#include <mma.h>
#include <math.h>
#include <stdint.h>

using namespace nvcuda;

#define NB    4096
#define NFG_  1024
#define NFP_  256
#define NFR_  256
#define NG_   4
#define FPPD  1280
#define THR2  302.76f                      // (0.2*87)^2
#define SIMSCALE 0.044194173824159216f     // 1/sqrt(512)

// ---------------- device scratch (static, allocation-free) ----------------
__device__ float  g_foot[NB * 2];
__device__ __half g_fpp_h [(size_t)NB * FPPD];
__device__ __half g_thW_h [(size_t)NG_ * FPPD * NFR_];
__device__ __half g_phW_h [(size_t)NG_ * FPPD * NFR_];
__device__ __half g_gwW_h [(size_t)NG_ * NFG_ * NFG_];
__device__ __half g_ft_h  [(size_t)NB * NFG_];
__device__ __half g_theta_h[(size_t)NG_ * NB * NFR_];
__device__ __half g_phi_h  [(size_t)NG_ * NB * NFR_];
__device__ __half g_A_h  [(size_t)NG_ * NB * NB];        // sim fp16 -> A in place
__device__ __half g_agg_h[(size_t)NG_ * NB * NFG_];
__device__ float  g_outp [(size_t)NG_ * NB * NFG_];

// ---------------- cp.async helpers ----------------
__device__ __forceinline__ void cp_async16(void* smem_dst, const void* gmem_src) {
    unsigned s = (unsigned)__cvta_generic_to_shared(smem_dst);
    asm volatile("cp.async.cg.shared.global [%0], [%1], 16;\n" :: "r"(s), "l"(gmem_src));
}
#define CP_COMMIT() asm volatile("cp.async.commit_group;\n" ::: "memory")

// ---------------- foot points ----------------
__global__ void foot_kernel(const float* __restrict__ boxes, float* __restrict__ foot) {
    int n = blockIdx.x * 256 + threadIdx.x;
    if (n < NB) {
        foot[2 * n]     = (boxes[4 * n + 0] + boxes[4 * n + 2]) * 0.5f;
        foot[2 * n + 1] = boxes[4 * n + 3];
    }
}

// ---------------- fpp (fp16) = [sincos_emb(foot,256) | feats] ----------------
__global__ void fpp_kernel(const float* __restrict__ feats,
                           const float* __restrict__ foot,
                           __half* __restrict__ fpp) {
    long long idx = (long long)blockIdx.x * 256 + threadIdx.x;
    if (idx >= (long long)NB * FPPD) return;
    int n = (int)(idx / FPPD);
    int j = (int)(idx % FPPD);
    float v;
    if (j < NFP_) {
        int coord = j / 128;
        int jj = j % 128;
        int i = jj & 63;
        bool is_cos = jj >= 64;
        float freq = expf(-(float)i * 0.14391157750382243f);  // 10000^(-i/64)
        float ang = foot[2 * n + coord] * freq;
        v = is_cos ? cosf(ang) : sinf(ang);
    } else {
        v = feats[(long long)n * NFG_ + (j - NFP_)];
    }
    fpp[idx] = __float2half(v);
}

// ---------------- elementwise fp32 -> fp16 ----------------
__global__ void conv_kernel(const float* __restrict__ in, __half* __restrict__ out, long long n) {
    long long i = ((long long)blockIdx.x * 256 + threadIdx.x) * 4;
    if (i >= n) return;
    float4 v = *(const float4*)(in + i);
    __half2 h0 = __floats2half2_rn(v.x, v.y);
    __half2 h1 = __floats2half2_rn(v.z, v.w);
    *(uint2*)(out + i) = make_uint2(*(uint32_t*)&h0, *(uint32_t*)&h1);
}

// ======================= fp16 wmma GEMM (R5 mainloop + fused epilogue) =======
// 128x128 block, BK=32, 8 warps 2x4, warp tile 64x32 (4x2 frags).
// TRANSB=0: B is [K,N] row-major; TRANSB=1: B is [N,K] row-major (A @ B^T).
// OUTH=1: fp16 out via smem staging (+BIAS per column); OUTH=0: fp32 out.
#define GBM 128
#define GBN 128
#define GBK 32
#define APAD 40     // halves per A row (32 + 8)
#define BPAD 136    // halves per B row, nontrans (128 + 8)

template<int TRANSB, int OUTH, int BIAS>
__global__ __launch_bounds__(256, 2)
void hgemm_kernel(const __half* __restrict__ Aall, const __half* __restrict__ Ball,
                  float* __restrict__ Cfall, __half* __restrict__ Chall,
                  const float* __restrict__ bias,
                  int M, int N, int K,
                  long long sA, long long sB, long long sC)
{
    int g = blockIdx.z;
    const __half* A = Aall + (long long)g * sA;
    const __half* B = Ball + (long long)g * sB;

    __shared__ __align__(16) __half As[2][GBM][APAD];
    __shared__ __align__(16) __half Bs[2][TRANSB ? GBN * APAD : GBK * BPAD];

    int tid = threadIdx.x;
    int wid = tid >> 5, lane = tid & 31;
    int wr = wid >> 2;      // 0..1  -> 64-row group
    int wc = wid & 3;       // 0..3  -> 32-col group
    int rowBase = blockIdx.y * GBM;
    int colBase = blockIdx.x * GBN;

    using FragA  = wmma::fragment<wmma::matrix_a, 16, 16, 16, __half, wmma::row_major>;
    using FragBr = wmma::fragment<wmma::matrix_b, 16, 16, 16, __half, wmma::row_major>;
    using FragBc = wmma::fragment<wmma::matrix_b, 16, 16, 16, __half, wmma::col_major>;
    using FragC  = wmma::fragment<wmma::accumulator, 16, 16, 16, float>;

    FragC acc[4][2];
    #pragma unroll
    for (int i = 0; i < 4; i++)
        #pragma unroll
        for (int j = 0; j < 2; j++)
            wmma::fill_fragment(acc[i][j], 0.0f);

    int KT = K / GBK;
    int u0 = tid * 2;

    #define ISSUE(kt, buf) {                                                              \
        int k0 = (kt) * GBK;                                                              \
        _Pragma("unroll")                                                                 \
        for (int q = 0; q < 2; q++) {                                                     \
            int u = u0 + q;                                                               \
            int ar = u >> 2, ac = (u & 3) * 8;                                            \
            cp_async16(&As[buf][ar][ac], A + (long long)(rowBase + ar) * K + k0 + ac);    \
            if (TRANSB) {                                                                 \
                int br = u >> 2, bc = (u & 3) * 8;                                        \
                cp_async16(&Bs[buf][br * APAD + bc],                                      \
                           B + (long long)(colBase + br) * K + k0 + bc);                  \
            } else {                                                                      \
                int br = u >> 4, bc = (u & 15) * 8;                                       \
                cp_async16(&Bs[buf][br * BPAD + bc],                                      \
                           B + (long long)(k0 + br) * N + colBase + bc);                  \
            }                                                                             \
        }                                                                                 \
    }

    ISSUE(0, 0); CP_COMMIT();

    for (int kt = 0; kt < KT; kt++) {
        int buf = kt & 1;
        if (kt + 1 < KT) {
            ISSUE(kt + 1, buf ^ 1); CP_COMMIT();
            asm volatile("cp.async.wait_group 1;\n" ::: "memory");
        } else {
            asm volatile("cp.async.wait_group 0;\n" ::: "memory");
        }
        __syncthreads();

        #pragma unroll
        for (int ks = 0; ks < 2; ks++) {
            FragA af[4];
            #pragma unroll
            for (int i = 0; i < 4; i++)
                wmma::load_matrix_sync(af[i], &As[buf][wr * 64 + i * 16][ks * 16], APAD);
            if (TRANSB) {
                FragBc bf[2];
                #pragma unroll
                for (int j = 0; j < 2; j++)
                    wmma::load_matrix_sync(bf[j], &Bs[buf][(wc * 32 + j * 16) * APAD + ks * 16], APAD);
                #pragma unroll
                for (int i = 0; i < 4; i++)
                    #pragma unroll
                    for (int j = 0; j < 2; j++)
                        wmma::mma_sync(acc[i][j], af[i], bf[j], acc[i][j]);
            } else {
                FragBr bf[2];
                #pragma unroll
                for (int j = 0; j < 2; j++)
                    wmma::load_matrix_sync(bf[j], &Bs[buf][(ks * 16) * BPAD + wc * 32 + j * 16], BPAD);
                #pragma unroll
                for (int i = 0; i < 4; i++)
                    #pragma unroll
                    for (int j = 0; j < 2; j++)
                        wmma::mma_sync(acc[i][j], af[i], bf[j], acc[i][j]);
            }
        }
        __syncthreads();
    }
    #undef ISSUE

    if (OUTH) {
        // alias dead A smem as fp32 staging: 8 warps x (16 x 40 floats) = 5120 floats
        __syncthreads();
        float* stage = (float*)(&As[0][0][0]) + wid * (16 * 40);
        __half* Ch = Chall + (long long)g * sC;
        const float* bi = BIAS ? (bias + (long long)g * N) : nullptr;
        int r = lane & 15, seg = lane >> 4;          // 16 rows x 2 col-segments
        int gcol0 = colBase + wc * 32 + seg * 16;
        #pragma unroll 1
        for (int i = 0; i < 4; i++) {
            wmma::store_matrix_sync(stage,      acc[i][0], 40, wmma::mem_row_major);
            wmma::store_matrix_sync(stage + 16, acc[i][1], 40, wmma::mem_row_major);
            __syncwarp();
            int grow = rowBase + wr * 64 + i * 16 + r;
            __align__(16) __half2 hbuf[8];
            #pragma unroll
            for (int k = 0; k < 8; k++) {
                float v0 = stage[r * 40 + seg * 16 + 2 * k];
                float v1 = stage[r * 40 + seg * 16 + 2 * k + 1];
                if (BIAS) { v0 += bi[gcol0 + 2 * k]; v1 += bi[gcol0 + 2 * k + 1]; }
                hbuf[k] = __floats2half2_rn(v0, v1);
            }
            uint4* dst = (uint4*)(Ch + (long long)grow * N + gcol0);
            dst[0] = ((const uint4*)hbuf)[0];
            dst[1] = ((const uint4*)hbuf)[1];
            __syncwarp();
        }
    } else {
        float* C = Cfall + (long long)g * sC;
        #pragma unroll
        for (int i = 0; i < 4; i++)
            #pragma unroll
            for (int j = 0; j < 2; j++)
                wmma::store_matrix_sync(
                    C + (long long)(rowBase + wr * 64 + i * 16) * N + colBase + wc * 32 + j * 16,
                    acc[i][j], N, wmma::mem_row_major);
    }
}

// ---------------- fused scale + mask + row softmax, fp16 in-place ----------------
__global__ void softmax_kernel(__half* __restrict__ Ah, const float* __restrict__ foot) {
    int n = blockIdx.x;
    long long base = ((long long)blockIdx.y * NB + n) * NB;
    __half2* row2 = (__half2*)(Ah + base);
    __shared__ float red[256];
    int tid = threadIdx.x;
    float frx = foot[2 * n], fry = foot[2 * n + 1];

    float v0[8], v1[8];
    float m = -INFINITY;
    #pragma unroll
    for (int i = 0; i < 8; i++) {
        int p = tid + i * 256;                  // half2 index -> columns (2p, 2p+1)
        float2 s = __half22float2(row2[p]);
        int c = 2 * p;
        float dx0 = frx - foot[2 * c],     dy0 = fry - foot[2 * c + 1];
        float dx1 = frx - foot[2 * c + 2], dy1 = fry - foot[2 * c + 3];
        v0[i] = (dx0 * dx0 + dy0 * dy0 > THR2) ? -INFINITY : s.x * SIMSCALE;
        v1[i] = (dx1 * dx1 + dy1 * dy1 > THR2) ? -INFINITY : s.y * SIMSCALE;
        m = fmaxf(m, fmaxf(v0[i], v1[i]));
    }
    red[tid] = m; __syncthreads();
    for (int s = 128; s > 0; s >>= 1) { if (tid < s) red[tid] = fmaxf(red[tid], red[tid + s]); __syncthreads(); }
    m = red[0]; __syncthreads();
    float sum = 0.0f;
    #pragma unroll
    for (int i = 0; i < 8; i++) {
        v0[i] = __expf(v0[i] - m); v1[i] = __expf(v1[i] - m);
        sum += v0[i] + v1[i];
    }
    red[tid] = sum; __syncthreads();
    for (int s = 128; s > 0; s >>= 1) { if (tid < s) red[tid] += red[tid + s]; __syncthreads(); }
    float inv = 1.0f / red[0];
    #pragma unroll
    for (int i = 0; i < 8; i++)
        row2[tid + i * 256] = __floats2half2_rn(v0[i] * inv, v1[i] * inv);
}

// ---------------- final_graph = min(1, mean_g A) ----------------
__global__ void fg_kernel(const __half* __restrict__ Ah, float* __restrict__ fg) {
    long long p = (long long)blockIdx.x * 256 + threadIdx.x;   // half2 index
    const long long PER_G2 = (long long)NB * NB / 2;
    const __half2* a2 = (const __half2*)Ah;
    float2 s0 = __half22float2(a2[p]);
    float2 s1 = __half22float2(a2[p + PER_G2]);
    float2 s2 = __half22float2(a2[p + 2 * PER_G2]);
    float2 s3 = __half22float2(a2[p + 3 * PER_G2]);
    float2 r;
    r.x = fminf(0.25f * (s0.x + s1.x + s2.x + s3.x), 1.0f);
    r.y = fminf(0.25f * (s0.y + s1.y + s2.y + s3.y), 1.0f);
    *(float2*)(fg + 2 * p) = r;
}

// ---------------- LayerNorm + ReLU + sum over g ----------------
__global__ void ln_kernel(const float* __restrict__ outp,
                          const float* __restrict__ gamma,
                          const float* __restrict__ beta,
                          float* __restrict__ out) {
    int n = blockIdx.x;
    int tid = threadIdx.x;  // 256
    __shared__ float red[256];
    float accum[4] = {0.f, 0.f, 0.f, 0.f};
    for (int g = 0; g < NG_; g++) {
        const float* row = outp + ((long long)g * NB + n) * NFG_;
        float v[4];
        float s = 0.0f;
        #pragma unroll
        for (int i = 0; i < 4; i++) { v[i] = row[tid + i * 256]; s += v[i]; }
        red[tid] = s; __syncthreads();
        for (int st = 128; st > 0; st >>= 1) { if (tid < st) red[tid] += red[tid + st]; __syncthreads(); }
        float mean = red[0] * (1.0f / NFG_); __syncthreads();
        float s2 = 0.0f;
        #pragma unroll
        for (int i = 0; i < 4; i++) { float d = v[i] - mean; s2 += d * d; }
        red[tid] = s2; __syncthreads();
        for (int st = 128; st > 0; st >>= 1) { if (tid < st) red[tid] += red[tid + st]; __syncthreads(); }
        float inv = rsqrtf(red[0] * (1.0f / NFG_) + 1e-5f);
        __syncthreads();
        #pragma unroll
        for (int i = 0; i < 4; i++) {
            int c = tid + i * 256;
            float y = (v[i] - mean) * inv * gamma[g * NFG_ + c] + beta[g * NFG_ + c];
            accum[i] += fmaxf(y, 0.0f);
        }
    }
    #pragma unroll
    for (int i = 0; i < 4; i++)
        out[(long long)n * NFG_ + tid + i * 256] = accum[i];
}

// ======================= launch =======================
extern "C" void kernel_launch(void* const* d_in, const int* in_sizes, int n_in,
                              void* d_out, int out_size) {
    const float* feats   = (const float*)d_in[0];
    const float* boxes   = (const float*)d_in[1];
    const float* theta_w = (const float*)d_in[2];
    const float* theta_b = (const float*)d_in[3];
    const float* phi_w   = (const float*)d_in[4];
    const float* phi_b   = (const float*)d_in[5];
    const float* gcn_w   = (const float*)d_in[6];
    const float* ln_g    = (const float*)d_in[7];
    const float* ln_b    = (const float*)d_in[8];
    float* out = (float*)d_out;   // [4096*1024] out ++ [4096*4096] final_graph

    float *p_foot, *p_outp;
    __half *p_fpp, *p_thW, *p_phW, *p_gwW, *p_ft, *p_theta, *p_phi, *p_Ah, *p_agg;
    cudaGetSymbolAddress((void**)&p_foot, g_foot);
    cudaGetSymbolAddress((void**)&p_fpp,  g_fpp_h);
    cudaGetSymbolAddress((void**)&p_thW,  g_thW_h);
    cudaGetSymbolAddress((void**)&p_phW,  g_phW_h);
    cudaGetSymbolAddress((void**)&p_gwW,  g_gwW_h);
    cudaGetSymbolAddress((void**)&p_ft,   g_ft_h);
    cudaGetSymbolAddress((void**)&p_theta, g_theta_h);
    cudaGetSymbolAddress((void**)&p_phi,  g_phi_h);
    cudaGetSymbolAddress((void**)&p_Ah,   g_A_h);
    cudaGetSymbolAddress((void**)&p_agg,  g_agg_h);
    cudaGetSymbolAddress((void**)&p_outp, g_outp);

    // 1) foot + fpp(fp16)
    foot_kernel<<<(NB + 255) / 256, 256>>>(boxes, p_foot);
    long long fppN = (long long)NB * FPPD;
    fpp_kernel<<<(unsigned)((fppN + 255) / 256), 256>>>(feats, p_foot, p_fpp);

    // 2) fp16 operand conversions
    {
        long long nw = (long long)NG_ * FPPD * NFR_;
        conv_kernel<<<(unsigned)(nw / 4 / 256), 256>>>(theta_w, p_thW, nw);
        conv_kernel<<<(unsigned)(nw / 4 / 256), 256>>>(phi_w, p_phW, nw);
        long long ng = (long long)NG_ * NFG_ * NFG_;
        conv_kernel<<<(unsigned)(ng / 4 / 256), 256>>>(gcn_w, p_gwW, ng);
        long long nf = (long long)NB * NFG_;
        conv_kernel<<<(unsigned)(nf / 4 / 256), 256>>>(feats, p_ft, nf);
    }

    // 3) theta/phi: [4096,1280] @ [1280,256] + bias -> fp16 (fused)
    {
        dim3 grid(NFR_ / GBN, NB / GBM, NG_);   // (2, 32, 4)
        hgemm_kernel<0,1,1><<<grid, 256>>>(p_fpp, p_thW, nullptr, p_theta, theta_b,
                                           NB, NFR_, FPPD,
                                           0, (long long)FPPD * NFR_, (long long)NB * NFR_);
        hgemm_kernel<0,1,1><<<grid, 256>>>(p_fpp, p_phW, nullptr, p_phi, phi_b,
                                           NB, NFR_, FPPD,
                                           0, (long long)FPPD * NFR_, (long long)NB * NFR_);
    }

    // 4) sim = theta @ phi^T -> fp16 (A buffer)
    {
        dim3 grid(NB / GBN, NB / GBM, NG_);     // (32, 32, 4)
        hgemm_kernel<1,1,0><<<grid, 256>>>(p_theta, p_phi, nullptr, p_Ah, nullptr,
                                           NB, NB, NFR_,
                                           (long long)NB * NFR_, (long long)NB * NFR_,
                                           (long long)NB * NB);
    }

    // 5) softmax (scale + mask fused), fp16 in-place
    softmax_kernel<<<dim3(NB, NG_), 256>>>(p_Ah, p_foot);

    // 6) final_graph
    fg_kernel<<<(NB * NB / 2) / 256, 256>>>(p_Ah, out + (long long)NB * NFG_);

    // 7) agg = A @ feats -> fp16 (fused)
    {
        dim3 grid(NFG_ / GBN, NB / GBM, NG_);   // (8, 32, 4)
        hgemm_kernel<0,1,0><<<grid, 256>>>(p_Ah, p_ft, nullptr, p_agg, nullptr,
                                           NB, NFG_, NB,
                                           (long long)NB * NB, 0, (long long)NB * NFG_);
    }

    // 8) outp = agg @ gcn_w -> fp32
    {
        dim3 grid(NFG_ / GBN, NB / GBM, NG_);   // (8, 32, 4)
        hgemm_kernel<0,0,0><<<grid, 256>>>(p_agg, p_gwW, p_outp, nullptr, nullptr,
                                           NB, NFG_, NFG_,
                                           (long long)NB * NFG_, (long long)NFG_ * NFG_,
                                           (long long)NB * NFG_);
    }

    // 9) LN + ReLU + sum over g
    ln_kernel<<<NB, 256>>>(p_outp, ln_g, ln_b, out);
}